// round 17
// baseline (speedup 1.0000x reference)
#include <cuda_runtime.h>
#include <cstdint>

// ---------------------------------------------------------------------------
// Problem constants
// ---------------------------------------------------------------------------
constexpr int R     = 128;   // rank (i, k)
constexpr int D     = 128;   // input dim (j)
constexpr int M_OUT = 32;    // output dim
constexpr int NB    = 128;   // batch N
constexpr int L     = 512;   // sequence length

constexpr int CHUNK_T = 64;           // time chunk (double-buffered)
constexpr int NCHUNKS = L / CHUNK_T;  // 8
constexpr int T_PER   = 4;            // steps per G CTA
constexpr int JC      = 32;           // j chunk width
constexpr int NTILES  = T_PER * 4;    // j-chunk tiles per CTA (16)

// Device-global scratch (~1.11 GB total .bss — inside aarch64 reloc reach)
__device__ float g_G[2][(size_t)CHUNK_T * NB * R * R];  // 2 x 512MB ping-pong
__device__ float g_h[NB * R];                           // carried hidden state
__device__ float g_Xt[(size_t)L * D * NB];              // X as [t][j][n]

// ---------------------------------------------------------------------------
// cp.async helpers (sm_80+, no arch-a features)
// ---------------------------------------------------------------------------
__device__ __forceinline__ void cp_async16(uint32_t dst_smem, const void* src) {
    asm volatile("cp.async.cg.shared.global [%0], [%1], 16;"
                 :: "r"(dst_smem), "l"(src) : "memory");
}
__device__ __forceinline__ void cp_async_commit() {
    asm volatile("cp.async.commit_group;" ::: "memory");
}
template <int N>
__device__ __forceinline__ void cp_async_wait() {
    asm volatile("cp.async.wait_group %0;" :: "n"(N) : "memory");
}

// ---------------------------------------------------------------------------
// Prep: transpose x [n][t][j] -> Xt [t][j][n]  (smem-tiled, coalesced both
// ways). grid = (L, 16): blockIdx.y -> (j-tile, n-tile) of 32x32.
// One 32x32 tile = 256 float4 = exactly one load + one store per thread.
// ---------------------------------------------------------------------------
__global__ void transpose_x_kernel(const float* __restrict__ X) {
    __shared__ float smT[32][33];        // [j_local][n_local], padded
    const int t  = blockIdx.x;
    const int jt = (blockIdx.y >> 2) * 32;
    const int nt = (blockIdx.y & 3) * 32;
    const int tid = threadIdx.x;

    // Load: thread -> (n_local = tid>>3, j-float4 = tid&7). 128B rows in X.
    {
        const int nl = tid >> 3;         // 0..31
        const int j4 = tid & 7;          // 0..7
        const float4 v = *reinterpret_cast<const float4*>(
            X + ((size_t)(nt + nl) * L + t) * D + jt + j4 * 4);
        smT[j4 * 4 + 0][nl] = v.x;
        smT[j4 * 4 + 1][nl] = v.y;
        smT[j4 * 4 + 2][nl] = v.z;
        smT[j4 * 4 + 3][nl] = v.w;
    }
    __syncthreads();

    // Store: thread -> (j_local = tid>>3, n-float4 = tid&7). Contiguous in Xt.
    {
        const int jl = tid >> 3;         // 0..31
        const int n4 = tid & 7;          // 0..7
        float4 v;
        v.x = smT[jl][n4 * 4 + 0];
        v.y = smT[jl][n4 * 4 + 1];
        v.z = smT[jl][n4 * 4 + 2];
        v.w = smT[jl][n4 * 4 + 3];
        *reinterpret_cast<float4*>(
            g_Xt + ((size_t)t * D + jt + jl) * NB + nt + n4 * 4) = v;
    }
}

// ---------------------------------------------------------------------------
// Phase 1: G[tl][ib][n][k] = sum_j Xt[t][j][n] * A[ib][j][k]
// CTA = (ib, t-group of T_PER). A[ib] (64KB) smem-resident.
// Warp-private X staging via cp.async: warp w computes n rows 16w..16w+15 and
// copies exactly that 64B column slice of every j-row ([t][j][n] layout is
// n-contiguous). Producer == consumer -> no CTA barriers; 3-deep async ring;
// per-tile sync = cp.async.wait_group + __syncwarp only. No main-loop STS.
// ---------------------------------------------------------------------------
constexpr int XS_W   = 128;                               // n per j-row
constexpr int XS_BUF = JC * XS_W;                         // 4096 floats / buffer
constexpr int SMEM_G = (128 * 128 + 3 * XS_BUF) * 4;      // 112 KB (2 CTA/SM)

__global__ __launch_bounds__(256, 2) void compute_G_kernel(
    const float* __restrict__ A,   // [R][D][R]
    int chunk_base, int gbuf)
{
    extern __shared__ float sm[];
    float* As = sm;                      // [j][k] 128x128
    float* Xs = sm + 128 * 128;          // [3][j=32][n=128]

    const int ib   = blockIdx.x;
    const int tg   = blockIdx.y;
    const int t0   = chunk_base + tg * T_PER;
    const int tid  = threadIdx.x;
    const int wid  = tid >> 5;           // warp 0..7 -> n rows 16w..16w+15
    const int lane = tid & 31;
    const int tx   = tid & 15;           // k pairs: 2*tx + 32*q
    const int ty   = tid >> 4;           // n rows ty*8 .. +7

    // Load A slab once (coalesced LDG.128 -> STS.128)
    {
        const float4* src = reinterpret_cast<const float4*>(A + (size_t)ib * D * R);
        float4* dst = reinterpret_cast<float4*>(As);
        #pragma unroll
        for (int q = 0; q < 16; ++q) dst[tid + 256 * q] = src[tid + 256 * q];
    }

    alignas(16) unsigned long long c2[8][4];
    #pragma unroll
    for (int m = 0; m < 8; ++m)
        #pragma unroll
        for (int p = 0; p < 4; ++p) c2[m][p] = 0ull;

    // Warp-private async copy of tile cc into ring buffer rb.
    // lane+32q -> (j = idx>>2, seg = idx&3): 4 x 16B per j-row = warp's slice.
    uint32_t xs_base;
    {
        const uint64_t gp = __cvta_generic_to_shared(Xs);
        xs_base = (uint32_t)gp;
    }
    auto CPX = [&](int cc, int rb) {
        const int t  = t0 + (cc >> 2);
        const int jc = (cc & 3) * JC;
        #pragma unroll
        for (int q = 0; q < 4; ++q) {
            const int idx = lane + 32 * q;        // 0..127
            const int j   = idx >> 2;             // 0..31
            const int seg = idx & 3;              // 16B segment
            const float* src =
                g_Xt + ((size_t)t * D + jc + j) * NB + 16 * wid + seg * 4;
            const uint32_t dst =
                xs_base + (uint32_t)(rb * XS_BUF + j * XS_W + 16 * wid + seg * 4) * 4u;
            cp_async16(dst, src);
        }
        cp_async_commit();
    };

    __syncthreads();                 // A slab visible to all warps
    CPX(0, 0);
    CPX(1, 1);

    for (int cc = 0; cc < NTILES; ++cc) {
        const int rb = cc % 3;
        if (cc + 2 < NTILES) CPX(cc + 2, (cc + 2) % 3);   // keep 2 in flight

        // Wait so that tile cc's group is complete (<=2 / <=1 / 0 pending).
        if (cc + 2 < NTILES) cp_async_wait<2>();
        else if (cc + 1 < NTILES) cp_async_wait<1>();
        else cp_async_wait<0>();
        __syncwarp();

        const float* xb = Xs + rb * XS_BUF;

        #pragma unroll
        for (int jj = 0; jj < JC; ++jj) {
            // a: 8 contiguous n-floats -> 2x LDS.128 (broadcast phases)
            float a[8];
            const float* ar = xb + jj * XS_W + ty * 8;
            *reinterpret_cast<float4*>(&a[0]) =
                *reinterpret_cast<const float4*>(ar);
            *reinterpret_cast<float4*>(&a[4]) =
                *reinterpret_cast<const float4*>(ar + 4);

            // b: 4 k-pairs at stride 32 floats
            const unsigned long long* br =
                reinterpret_cast<const unsigned long long*>(
                    As + ((cc & 3) * JC + jj) * 128);
            unsigned long long b2[4];
            #pragma unroll
            for (int q = 0; q < 4; ++q) b2[q] = br[tx + 16 * q];

            #pragma unroll
            for (int m = 0; m < 8; ++m) {
                unsigned long long a2;
                const unsigned int au = __float_as_uint(a[m]);
                asm("mov.b64 %0, {%1, %1};" : "=l"(a2) : "r"(au));
                #pragma unroll
                for (int q = 0; q < 4; ++q)
                    asm("fma.rn.f32x2 %0, %1, %2, %0;"
                        : "+l"(c2[m][q]) : "l"(a2), "l"(b2[q]));
            }
        }

        if ((cc & 3) == 3) {         // end of a t: write G, reset accumulators
            const int tl = tg * T_PER + (cc >> 2);
            float* gb = g_G[gbuf] + ((size_t)tl * R + ib) * ((size_t)NB * R);
            #pragma unroll
            for (int m = 0; m < 8; ++m) {
                unsigned long long* drow =
                    reinterpret_cast<unsigned long long*>(gb + (ty * 8 + m) * 128);
                #pragma unroll
                for (int q = 0; q < 4; ++q) {
                    drow[tx + 16 * q] = c2[m][q];  // STG.64, warp-contiguous
                    c2[m][q] = 0ull;
                }
            }
        }
    }
}

// ---------------------------------------------------------------------------
// Phase 2: scan (DRAM-bound, 84%). Forked stream, overlaps next chunk's G.
// G layout [tl][i][n][k].
// ---------------------------------------------------------------------------
__global__ __launch_bounds__(512, 1) void scan_kernel(
    const float* __restrict__ alpha,
    const float* __restrict__ Omega,
    float* __restrict__ out,
    int is_first, int is_last, int gbuf)
{
    const int n   = blockIdx.x;
    const int tid = threadIdx.x;
    const int w   = tid >> 5;
    const int l   = tid & 31;

    __shared__ float h[128];
    __shared__ float part[16][128];

    if (tid < 128) h[tid] = is_first ? alpha[tid] : g_h[n * R + tid];
    __syncthreads();

    const float* Gb = g_G[gbuf];
    float4 ga[8], gb_[8];

#define LOADG(dst, tl_) {                                                     \
    _Pragma("unroll")                                                         \
    for (int m = 0; m < 8; ++m)                                               \
        dst[m] = *reinterpret_cast<const float4*>(                            \
            Gb + ((size_t)(tl_) * R + (w + 16 * m)) * ((size_t)NB * R)        \
               + (size_t)n * R + l * 4);                                      \
}

#define STEP(cur, nxt, tl_) {                                                 \
    const int tp = ((tl_) + 1 < CHUNK_T) ? (tl_) + 1 : CHUNK_T - 1;           \
    LOADG(nxt, tp);                                                           \
    float4 acc = make_float4(0.f, 0.f, 0.f, 0.f);                             \
    _Pragma("unroll")                                                         \
    for (int m = 0; m < 8; ++m) {                                             \
        const float hv = h[w + 16 * m];                                       \
        acc.x = fmaf(hv, cur[m].x, acc.x);                                    \
        acc.y = fmaf(hv, cur[m].y, acc.y);                                    \
        acc.z = fmaf(hv, cur[m].z, acc.z);                                    \
        acc.w = fmaf(hv, cur[m].w, acc.w);                                    \
    }                                                                         \
    *reinterpret_cast<float4*>(&part[w][l * 4]) = acc;                        \
    __syncthreads();                                                          \
    if (tid < 128) {                                                          \
        float s = part[0][tid];                                               \
        _Pragma("unroll")                                                     \
        for (int q = 1; q < 16; ++q) s += part[q][tid];                       \
        h[tid] = s;                                                           \
    }                                                                         \
    __syncthreads();                                                          \
}

    LOADG(ga, 0);
    for (int tl = 0; tl < CHUNK_T; tl += 2) {
        STEP(ga, gb_, tl);
        STEP(gb_, ga, tl + 1);
    }
#undef STEP
#undef LOADG

    if (is_last) {
        if (tid < M_OUT) {
            float s = 0.f;
            #pragma unroll 4
            for (int k = 0; k < R; ++k)
                s = fmaf(h[k], Omega[k * M_OUT + tid], s);
            out[n * M_OUT + tid] = s;
        }
    } else {
        if (tid < 128) g_h[n * R + tid] = h[tid];
    }
}

// ---------------------------------------------------------------------------
// Launch. Main stream: G chunks; forked stream: scans on the other G buffer.
// scan(c) waits G(c); G(c+2) waits scan(c); join before capture ends.
// ---------------------------------------------------------------------------
extern "C" void kernel_launch(void* const* d_in, const int* in_sizes, int n_in,
                              void* d_out, int out_size)
{
    (void)in_sizes; (void)n_in; (void)out_size;
    const float* x     = (const float*)d_in[0];
    const float* alpha = (const float*)d_in[1];
    const float* A     = (const float*)d_in[2];
    const float* Omega = (const float*)d_in[3];
    float* out = (float*)d_out;

    static cudaStream_t s2 = nullptr;
    static cudaEvent_t evG[NCHUNKS], evS[NCHUNKS];
    static bool init_done = false;
    if (!init_done) {
        cudaFuncSetAttribute(compute_G_kernel,
                             cudaFuncAttributeMaxDynamicSharedMemorySize, SMEM_G);
        cudaStreamCreateWithFlags(&s2, cudaStreamNonBlocking);
        for (int c = 0; c < NCHUNKS; ++c) {
            cudaEventCreateWithFlags(&evG[c], cudaEventDisableTiming);
            cudaEventCreateWithFlags(&evS[c], cudaEventDisableTiming);
        }
        init_done = true;
    }

    {   // one-time X transpose [n][t][j] -> [t][j][n] (~20us)
        dim3 tgrid(L, 16);
        transpose_x_kernel<<<tgrid, 256>>>(x);
    }

    for (int c = 0; c < NCHUNKS; ++c) {
        const int buf = c & 1;
        if (c >= 2) cudaStreamWaitEvent((cudaStream_t)0, evS[c - 2], 0);
        dim3 grid1(R, CHUNK_T / T_PER);     // 128 ib x 16 t-groups
        compute_G_kernel<<<grid1, 256, SMEM_G>>>(A, c * CHUNK_T, buf);
        cudaEventRecord(evG[c], (cudaStream_t)0);
        cudaStreamWaitEvent(s2, evG[c], 0);
        scan_kernel<<<NB, 512, 0, s2>>>(alpha, Omega, out,
                                        c == 0 ? 1 : 0,
                                        c == NCHUNKS - 1 ? 1 : 0, buf);
        cudaEventRecord(evS[c], s2);
    }
    cudaStreamWaitEvent((cudaStream_t)0, evS[NCHUNKS - 1], 0);
}